// round 2
// baseline (speedup 1.0000x reference)
#include <cuda_runtime.h>
#include <cstdint>

// ---------------------------------------------------------------------------
// QLoRA 4-bit: y = x @ (dequant(W)^T + 2 * W_a @ W_b)
// Strategy: prologue folds NF4-dequant + LoRA into W_eff[OUT][IN] (tf32-rounded
// fp32 in __device__ scratch), then one TF32 tensor-core GEMM.
// ---------------------------------------------------------------------------

namespace {
constexpr int D_IN  = 4096;
constexpr int D_OUT = 4096;
constexpr int M_TOK = 4 * 2048;   // B*S
constexpr int RNK   = 16;

constexpr int BM = 128, BN = 128, BK = 16, KPAD = 20;
constexpr int NTHREADS = 256;
}

// 64 MB scratch for the folded weight (allocation-free rule: __device__ global)
__device__ __align__(16) float d_Weff[(size_t)D_OUT * D_IN];

__constant__ float c_nf4[16] = {
    -1.0f, -0.6961928009986877f, -0.5250730514526367f, -0.39491748809814453f,
    -0.28444138169288635f, -0.18477343022823334f, -0.09105003625154495f, 0.0f,
    0.07958029955625534f, 0.16093020141124725f, 0.24611230194568634f,
    0.33791524171829224f, 0.44070982933044434f, 0.5626170039176941f,
    0.7229568362236023f, 1.0f};

__device__ __forceinline__ unsigned f2tf32(float x) {
    unsigned r;
    asm("cvt.rna.tf32.f32 %0, %1;" : "=r"(r) : "f"(x));
    return r;
}

__device__ __forceinline__ void cp_async16(void* smem, const void* gmem) {
    unsigned s = (unsigned)__cvta_generic_to_shared(smem);
    asm volatile("cp.async.ca.shared.global [%0], [%1], 16;\n" :: "r"(s), "l"(gmem));
}

// ---------------------------------------------------------------------------
// Prologue: W_eff[n][k] = nf4[codes[n][k]] * absmax[n][k/64] + 2*sum_r Wa[k][r]*Wb[r][n]
// Stored row-major [OUT][IN] (K contiguous) = exactly the "col" (K-major) B
// operand layout the mma wants. Pre-rounded to tf32 (rna) so the GEMM skips
// B-side cvt and avoids truncation bias.
// ---------------------------------------------------------------------------
__global__ void build_weff_kernel(const int* __restrict__ codes,
                                  const float* __restrict__ absmax,
                                  const float* __restrict__ Wa,
                                  const float* __restrict__ Wb) {
    const int n = blockIdx.x;
    float wb[RNK];
#pragma unroll
    for (int r = 0; r < RNK; r++) wb[r] = __ldg(&Wb[r * D_OUT + n]);

    const int*   crow = codes  + (size_t)n * D_IN;
    const float* am   = absmax + (size_t)n * (D_IN / 64);
    float*       orow = d_Weff + (size_t)n * D_IN;

    for (int k = threadIdx.x; k < D_IN; k += blockDim.x) {
        float w = c_nf4[crow[k] & 15] * am[k >> 6];
        const float4* wa = reinterpret_cast<const float4*>(Wa + (size_t)k * RNK);
        float4 a0 = wa[0], a1 = wa[1], a2 = wa[2], a3 = wa[3];
        float l = a0.x * wb[0]  + a0.y * wb[1]  + a0.z * wb[2]  + a0.w * wb[3]
                + a1.x * wb[4]  + a1.y * wb[5]  + a1.z * wb[6]  + a1.w * wb[7]
                + a2.x * wb[8]  + a2.y * wb[9]  + a2.z * wb[10] + a2.w * wb[11]
                + a3.x * wb[12] + a3.y * wb[13] + a3.z * wb[14] + a3.w * wb[15];
        float v = w + 2.0f * l;          // SCALE = 32/16 = 2
        orow[k] = __uint_as_float(f2tf32(v));
    }
}

// ---------------------------------------------------------------------------
// TF32 GEMM: C[M][N] = A[M][K] * W_eff[N][K]^T
// 128x128x16 block tile, 8 warps (4 along M x 2 along N), warp tile 32x64,
// m16n8k8 tf32 mma, cp.async double buffer, KPAD=20 -> conflict-free LDS.
// ---------------------------------------------------------------------------
__global__ __launch_bounds__(NTHREADS, 1)
void qgemm_kernel(const float* __restrict__ A, float* __restrict__ C) {
    __shared__ __align__(16) float As[2][BM][KPAD];
    __shared__ __align__(16) float Bs[2][BN][KPAD];

    const int tid   = threadIdx.x;
    const int lane  = tid & 31;
    const int warp  = tid >> 5;
    const int gid   = lane >> 2;   // group id 0..7
    const int tig   = lane & 3;    // thread-in-group 0..3
    const int warpM = warp & 3;    // 32-row slab
    const int warpN = warp >> 2;   // 64-col slab

    const int mBase = blockIdx.y * BM;
    const int nBase = blockIdx.x * BN;

    const int ldRow = tid >> 2;        // 0..63
    const int ldCol = (tid & 3) << 2;  // 0,4,8,12

    const float* Agp = A      + (size_t)(mBase + ldRow) * D_IN + ldCol;
    const float* Bgp = d_Weff + (size_t)(nBase + ldRow) * D_IN + ldCol;

    float acc[2][8][4];
#pragma unroll
    for (int i = 0; i < 2; i++)
#pragma unroll
        for (int j = 0; j < 8; j++)
#pragma unroll
            for (int v = 0; v < 4; v++) acc[i][j][v] = 0.f;

    const int nt = D_IN / BK;  // 256

    // prologue: stage 0 and 1
#pragma unroll
    for (int s = 0; s < 2; s++) {
        const int k0 = s * BK;
#pragma unroll
        for (int h = 0; h < 2; h++) {
            cp_async16(&As[s][ldRow + 64 * h][ldCol], Agp + (size_t)64 * h * D_IN + k0);
            cp_async16(&Bs[s][ldRow + 64 * h][ldCol], Bgp + (size_t)64 * h * D_IN + k0);
        }
        asm volatile("cp.async.commit_group;\n");
    }

    for (int kt = 0; kt < nt; kt++) {
        asm volatile("cp.async.wait_group 1;\n");
        __syncthreads();
        const int buf = kt & 1;

#pragma unroll
        for (int kk = 0; kk < BK; kk += 8) {
            unsigned a[2][4];
#pragma unroll
            for (int mi = 0; mi < 2; mi++) {
                const int r = warpM * 32 + mi * 16 + gid;
                a[mi][0] = f2tf32(As[buf][r    ][kk + tig]);
                a[mi][1] = f2tf32(As[buf][r + 8][kk + tig]);
                a[mi][2] = f2tf32(As[buf][r    ][kk + tig + 4]);
                a[mi][3] = f2tf32(As[buf][r + 8][kk + tig + 4]);
            }
            unsigned b[8][2];
#pragma unroll
            for (int ni = 0; ni < 8; ni++) {
                const int c = warpN * 64 + ni * 8 + gid;
                b[ni][0] = __float_as_uint(Bs[buf][c][kk + tig]);      // pre-rounded
                b[ni][1] = __float_as_uint(Bs[buf][c][kk + tig + 4]);
            }
#pragma unroll
            for (int mi = 0; mi < 2; mi++)
#pragma unroll
                for (int ni = 0; ni < 8; ni++) {
                    asm volatile(
                        "mma.sync.aligned.m16n8k8.row.col.f32.tf32.tf32.f32 "
                        "{%0,%1,%2,%3}, {%4,%5,%6,%7}, {%8,%9}, {%0,%1,%2,%3};\n"
                        : "+f"(acc[mi][ni][0]), "+f"(acc[mi][ni][1]),
                          "+f"(acc[mi][ni][2]), "+f"(acc[mi][ni][3])
                        : "r"(a[mi][0]), "r"(a[mi][1]), "r"(a[mi][2]), "r"(a[mi][3]),
                          "r"(b[ni][0]), "r"(b[ni][1]));
                }
        }
        __syncthreads();

        if (kt + 2 < nt) {
            const int k0 = (kt + 2) * BK;
#pragma unroll
            for (int h = 0; h < 2; h++) {
                cp_async16(&As[buf][ldRow + 64 * h][ldCol], Agp + (size_t)64 * h * D_IN + k0);
                cp_async16(&Bs[buf][ldRow + 64 * h][ldCol], Bgp + (size_t)64 * h * D_IN + k0);
            }
        }
        asm volatile("cp.async.commit_group;\n");
    }

    // epilogue: direct float2 stores
#pragma unroll
    for (int mi = 0; mi < 2; mi++) {
        const int row0 = mBase + warpM * 32 + mi * 16 + gid;
#pragma unroll
        for (int ni = 0; ni < 8; ni++) {
            const int col = nBase + warpN * 64 + ni * 8 + tig * 2;
            float2 v01 = make_float2(acc[mi][ni][0], acc[mi][ni][1]);
            float2 v23 = make_float2(acc[mi][ni][2], acc[mi][ni][3]);
            *reinterpret_cast<float2*>(C + (size_t)row0 * D_OUT + col)       = v01;
            *reinterpret_cast<float2*>(C + (size_t)(row0 + 8) * D_OUT + col) = v23;
        }
    }
}

// ---------------------------------------------------------------------------
extern "C" void kernel_launch(void* const* d_in, const int* in_sizes, int n_in,
                              void* d_out, int out_size) {
    const float* x      = (const float*)d_in[0];
    const int*   codes  = (const int*)  d_in[1];
    const float* absmax = (const float*)d_in[2];
    const float* Wa     = (const float*)d_in[3];
    const float* Wb     = (const float*)d_in[4];
    float* out = (float*)d_out;

    build_weff_kernel<<<D_OUT, 256>>>(codes, absmax, Wa, Wb);

    dim3 grid(D_OUT / BN, M_TOK / BM);   // N-fast for L2 reuse of W_eff panel
    qgemm_kernel<<<grid, NTHREADS>>>(x, out);
}